// round 4
// baseline (speedup 1.0000x reference)
#include <cuda_runtime.h>

#define NN   4096
#define TT   300
#define TW   10          // 320 bits >= 300 timesteps
#define NBLK 128         // persistent blocks (co-resident; 148 SMs)
#define NTHR 256

// ---------------- device scratch (static globals; no allocations) ----------------
__device__ unsigned           g_mask[NN * TW];          // bit t of inp[t][i], i-major
__device__ float              g_Xpart[4ull * 320 * NN]; // 4 i-quarter partials of inp@W
__device__ unsigned long long g_slot[TT][NBLK];         // {tag=t+1, spike mask}
__device__ unsigned           g_bar_count;
__device__ unsigned           g_bar_epoch;

__device__ __forceinline__ unsigned ldvolu(const unsigned* p) {
    unsigned v; asm volatile("ld.volatile.global.b32 %0, [%1];" : "=r"(v) : "l"(p)); return v;
}
__device__ __forceinline__ unsigned long long ldcg64(const unsigned long long* p) {
    unsigned long long v; asm volatile("ld.global.cg.b64 %0, [%1];" : "=l"(v) : "l"(p)); return v;
}
__device__ __forceinline__ void stcg64(unsigned long long* p, unsigned long long v) {
    asm volatile("st.global.cg.b64 [%0], %1;" :: "l"(p), "l"(v));
}

// central epoch barrier — phase transitions only; replay-safe
__device__ __forceinline__ void gbar(unsigned e0, unsigned n) {
    __syncthreads();
    if (threadIdx.x == 0) {
        __threadfence();
        if (atomicAdd(&g_bar_count, 1u) == NBLK - 1u) {
            *(volatile unsigned*)&g_bar_count = 0u;
            __threadfence();
            atomicAdd(&g_bar_epoch, 1u);
        } else {
            while (ldvolu(&g_bar_epoch) - e0 < n) {}
        }
        __threadfence();
    }
    __syncthreads();
}

__global__ void __launch_bounds__(NTHR, 1)
snn_kernel(const int* __restrict__ inp, const float* __restrict__ w,
           const float* __restrict__ w_rec, float* __restrict__ out)
{
    __shared__ unsigned long long Adup[128][18];   // phase-1 activation tiles
    __shared__ float part[2][8][33];               // double-buffered partial sums

    const int tid = threadIdx.x;
    const int bid = blockIdx.x;

    unsigned e0 = 0;
    if (tid == 0) e0 = ldvolu(&g_bar_epoch);       // epoch base (read before any arrival)

    // ---------------- phase 0: pack inp bits + clear slot tags -------------------
    for (int u = bid * NTHR + tid; u < TT * NBLK; u += NBLK * NTHR)
        g_slot[0][u] = 0ull;                       // flat clear (tags -> 0)
    for (int u = bid * NTHR + tid; u < NN * TW; u += NBLK * NTHR) {
        int word = u % TW;
        int i    = u / TW;
        unsigned m = 0u;
        int tb = word * 32;
        #pragma unroll
        for (int b = 0; b < 32; ++b) {
            int t = tb + b;
            if (t < TT) m |= (((unsigned)inp[(size_t)t * NN + i]) & 1u) << b;
        }
        g_mask[i * TW + word] = m;
    }
    gbar(e0, 1);

    // ---------------- phase 1: X partials via packed f32x2 FFMA (exact) ----------
    for (int tile = bid; tile < 640; tile += NBLK) {
        int word = tile % 10;
        int ccq  = tile / 10;
        int cc   = ccq >> 2;
        int q    = ccq & 3;
        int j    = cc * 256 + tid;
        int ibase = q * 1024;

        unsigned long long acc[16];
        #pragma unroll
        for (int k = 0; k < 16; ++k) acc[k] = 0ull;

        for (int sub = 0; sub < 8; ++sub) {
            int ib = ibase + sub * 128;
            __syncthreads();
            for (int e = tid; e < 2048; e += NTHR) {
                int ii = e >> 4, tp = e & 15;
                unsigned m  = g_mask[(ib + ii) * TW + word];
                unsigned lo = (m >> (2 * tp))     & 1u ? 0x3f800000u : 0u;
                unsigned hi = (m >> (2 * tp + 1)) & 1u ? 0x3f800000u : 0u;
                Adup[ii][tp] = ((unsigned long long)hi << 32) | lo;
            }
            __syncthreads();
            for (int ii = 0; ii < 128; ++ii) {
                unsigned wu = __float_as_uint(w[(size_t)(ib + ii) * NN + j]);
                unsigned long long wpk;
                asm("mov.b64 %0, {%1, %1};" : "=l"(wpk) : "r"(wu));
                const ulonglong2* ap = (const ulonglong2*)(&Adup[ii][0]);
                #pragma unroll
                for (int k = 0; k < 8; ++k) {
                    ulonglong2 a2 = ap[k];
                    asm("fma.rn.f32x2 %0, %1, %2, %0;" : "+l"(acc[2*k])   : "l"(wpk), "l"(a2.x));
                    asm("fma.rn.f32x2 %0, %1, %2, %0;" : "+l"(acc[2*k+1]) : "l"(wpk), "l"(a2.y));
                }
            }
        }
        #pragma unroll
        for (int tp = 0; tp < 16; ++tp) {
            int t0 = word * 32 + 2 * tp;
            g_Xpart[((size_t)q * 320 + t0)     * NN + j] = __uint_as_float((unsigned)acc[tp]);
            g_Xpart[((size_t)q * 320 + t0 + 1) * NN + j] = __uint_as_float((unsigned)(acc[tp] >> 32));
        }
    }
    gbar(e0, 2);

    // ---------------- phase 2: recurrent LIF, tagged-slot handshake --------------
    const int l  = tid & 31;       // lane
    const int wp = tid >> 5;       // warp 0..7
    const int j  = bid * 32 + l;   // this block's 32 output columns

    // gather word ranges for warps 1..7: 18,18,18,18,18,18,20 (=128 words)
    const int wstart = (wp >= 1) ? 18 * (wp - 1) : 0;
    const int wcnt   = (wp == 7) ? 20 : 18;

    float v = 0.f, rt = 0.f, tl = 1.f;
    const float DECAY = 0.99004983374916805f;   // fp32(exp(-1/100))

    for (int t = 0; t < TT; ++t) {
        float x0 = 0.f, x1 = 0.f, x2 = 0.f, x3 = 0.f;
        float xa = 0.f, xb = 0.f;

        if (wp == 0) {
            // warp 0: prefetch input drive only
            x0 = g_Xpart[(size_t)(0 * 320 + t) * NN + j];
            x1 = g_Xpart[(size_t)(1 * 320 + t) * NN + j];
            x2 = g_Xpart[(size_t)(2 * 320 + t) * NN + j];
            x3 = g_Xpart[(size_t)(3 * 320 + t) * NN + j];
        } else if (t > 0) {
            // one parallel wave of tagged-slot reads; retry only stale lanes
            const unsigned long long* slot = g_slot[t - 1];
            const unsigned want = (unsigned)t;            // producer tag = step+1
            unsigned long long u = 0ull;
            bool need = (l < wcnt);
            if (need) u = ldcg64(&slot[wstart + l]);
            while (1) {
                bool bad = need && ((unsigned)(u >> 32) != want);
                if (!__any_sync(0xffffffffu, bad)) break;
                if (bad) u = ldcg64(&slot[wstart + l]);
            }
            unsigned m32 = (unsigned)u;
            // gather w_rec rows for spiking neurons (2 accumulators for ILP)
            for (int k = 0; k < wcnt; ++k) {
                unsigned bits = __shfl_sync(0xffffffffu, m32, k);
                int base = (wstart + k) << 5;
                while (bits) {
                    int b0 = __ffs(bits) - 1; bits &= bits - 1u;
                    if (bits) {
                        int b1 = __ffs(bits) - 1; bits &= bits - 1u;
                        xa += __ldcg(&w_rec[(size_t)(base + b0) * NN + j]);
                        xb += __ldcg(&w_rec[(size_t)(base + b1) * NN + j]);
                    } else {
                        xa += __ldcg(&w_rec[(size_t)(base + b0) * NN + j]);
                    }
                }
            }
        }
        part[t & 1][wp][l] = xa + xb;
        __syncthreads();

        if (wp == 0) {
            const float (*pt)[33] = part[t & 1];
            float xt = ((pt[1][l] + pt[2][l]) + (pt[3][l] + pt[4][l]))
                     + ((pt[5][l] + pt[6][l]) + pt[7][l])
                     + ((x0 + x1) + (x2 + x3));
            // LIF dynamics, exact reference order
            v *= DECAY;
            float xin = (rt > 0.f) ? 0.f : xt;
            rt -= 1.f;
            v += xin;
            bool sp = (v >= 10.f);
            if (sp) { tl = (float)t / 300.0f; rt = 1.f; v = 0.f; }

            // publish FIRST (single atomic 64-bit tagged store), then outputs
            unsigned ball = __ballot_sync(0xffffffffu, sp);
            if (t < TT - 1 && l == 0)
                stcg64(&g_slot[t][bid],
                       ((unsigned long long)(unsigned)(t + 1) << 32) |
                       (unsigned long long)ball);
            out[(size_t)t * NN + j]            = sp ? 1.f : 0.f;
            out[(size_t)(TT + t) * NN + j]     = tl;
            out[(size_t)(2 * TT + t) * NN + j] = v;
        }
        // no trailing sync: part[] is double-buffered; any producer's step-t
        // publish transitively requires every block's step-(t-1) publish,
        // so a buffer slot is never overwritten before warp 0 has read it.
    }
}

// ---------------- launch ----------------
extern "C" void kernel_launch(void* const* d_in, const int* in_sizes, int n_in,
                              void* d_out, int out_size) {
    const int* inp; const float* w; const float* w_rec;
    if (in_sizes[0] == TT * NN) {
        inp = (const int*)d_in[0]; w = (const float*)d_in[1]; w_rec = (const float*)d_in[2];
    } else if (n_in > 1 && in_sizes[1] == TT * NN) {
        inp = (const int*)d_in[1]; w = (const float*)d_in[0]; w_rec = (const float*)d_in[2];
    } else {
        inp = (const int*)d_in[2]; w = (const float*)d_in[0]; w_rec = (const float*)d_in[1];
    }
    snn_kernel<<<NBLK, NTHR>>>(inp, w, w_rec, (float*)d_out);
}

// round 5
// speedup vs baseline: 1.2300x; 1.2300x over previous
#include <cuda_runtime.h>

#define NN   4096
#define TT   300
#define TW   10          // 320 bits >= 300 timesteps
#define NBLK 128         // persistent blocks (co-resident; 148 SMs)
#define NTHR 256

// ---------------- device scratch (static globals; no allocations) ----------------
__device__ unsigned                        g_mask[NN * TW];          // bit t of inp[t][i]
__device__ float                           g_Xpart[4ull * 320 * NN]; // 4 i-quarter partials
__device__ __align__(256) unsigned long long g_slot[TT][NBLK];       // {tag=t+1, spike mask}
__device__ unsigned                        g_bar_count;
__device__ unsigned                        g_bar_epoch;

__device__ __forceinline__ unsigned ldvolu(const unsigned* p) {
    unsigned v; asm volatile("ld.volatile.global.b32 %0, [%1];" : "=r"(v) : "l"(p)); return v;
}
__device__ __forceinline__ void ldcgv2(const unsigned long long* p,
                                       unsigned long long& a, unsigned long long& b) {
    asm volatile("ld.global.cg.v2.u64 {%0,%1}, [%2];" : "=l"(a), "=l"(b) : "l"(p));
}
__device__ __forceinline__ void stcg64(unsigned long long* p, unsigned long long v) {
    asm volatile("st.global.cg.b64 [%0], %1;" :: "l"(p), "l"(v));
}

// central epoch barrier — phase transitions only; replay-safe
__device__ __forceinline__ void gbar(unsigned e0, unsigned n) {
    __syncthreads();
    if (threadIdx.x == 0) {
        __threadfence();
        if (atomicAdd(&g_bar_count, 1u) == NBLK - 1u) {
            *(volatile unsigned*)&g_bar_count = 0u;
            __threadfence();
            atomicAdd(&g_bar_epoch, 1u);
        } else {
            while (ldvolu(&g_bar_epoch) - e0 < n) {}
        }
        __threadfence();
    }
    __syncthreads();
}

__global__ void __launch_bounds__(NTHR, 1)
snn_kernel(const int* __restrict__ inp, const float* __restrict__ w,
           const float* __restrict__ w_rec, float* __restrict__ out)
{
    __shared__ unsigned long long Adup[128][18];   // phase-1 activation tiles
    __shared__ float    part[8][33];               // phase-2 partial sums
    __shared__ unsigned sh_mask[128];              // step's spike masks (from poll warp)

    const int tid = threadIdx.x;
    const int bid = blockIdx.x;

    unsigned e0 = 0;
    if (tid == 0) e0 = ldvolu(&g_bar_epoch);       // epoch base (read before any arrival)

    // ---------------- phase 0: pack inp bits + clear slot tags -------------------
    for (int u = bid * NTHR + tid; u < TT * NBLK; u += NBLK * NTHR)
        g_slot[0][u] = 0ull;                       // flat clear (tags -> 0)
    for (int u = bid * NTHR + tid; u < NN * TW; u += NBLK * NTHR) {
        int word = u % TW;
        int i    = u / TW;
        unsigned m = 0u;
        int tb = word * 32;
        #pragma unroll
        for (int b = 0; b < 32; ++b) {
            int t = tb + b;
            if (t < TT) m |= (((unsigned)inp[(size_t)t * NN + i]) & 1u) << b;
        }
        g_mask[i * TW + word] = m;
    }
    gbar(e0, 1);

    // ---------------- phase 1: X partials via packed f32x2 FFMA (exact) ----------
    for (int tile = bid; tile < 640; tile += NBLK) {
        int word = tile % 10;
        int ccq  = tile / 10;
        int cc   = ccq >> 2;
        int q    = ccq & 3;
        int j    = cc * 256 + tid;
        int ibase = q * 1024;

        unsigned long long acc[16];
        #pragma unroll
        for (int k = 0; k < 16; ++k) acc[k] = 0ull;

        for (int sub = 0; sub < 8; ++sub) {
            int ib = ibase + sub * 128;
            __syncthreads();
            for (int e = tid; e < 2048; e += NTHR) {
                int ii = e >> 4, tp = e & 15;
                unsigned m  = g_mask[(ib + ii) * TW + word];
                unsigned lo = (m >> (2 * tp))     & 1u ? 0x3f800000u : 0u;
                unsigned hi = (m >> (2 * tp + 1)) & 1u ? 0x3f800000u : 0u;
                Adup[ii][tp] = ((unsigned long long)hi << 32) | lo;
            }
            __syncthreads();
            for (int ii = 0; ii < 128; ++ii) {
                unsigned wu = __float_as_uint(w[(size_t)(ib + ii) * NN + j]);
                unsigned long long wpk;
                asm("mov.b64 %0, {%1, %1};" : "=l"(wpk) : "r"(wu));
                const ulonglong2* ap = (const ulonglong2*)(&Adup[ii][0]);
                #pragma unroll
                for (int k = 0; k < 8; ++k) {
                    ulonglong2 a2 = ap[k];
                    asm("fma.rn.f32x2 %0, %1, %2, %0;" : "+l"(acc[2*k])   : "l"(wpk), "l"(a2.x));
                    asm("fma.rn.f32x2 %0, %1, %2, %0;" : "+l"(acc[2*k+1]) : "l"(wpk), "l"(a2.y));
                }
            }
        }
        #pragma unroll
        for (int tp = 0; tp < 16; ++tp) {
            int t0 = word * 32 + 2 * tp;
            g_Xpart[((size_t)q * 320 + t0)     * NN + j] = __uint_as_float((unsigned)acc[tp]);
            g_Xpart[((size_t)q * 320 + t0 + 1) * NN + j] = __uint_as_float((unsigned)(acc[tp] >> 32));
        }
    }
    gbar(e0, 2);

    // ---------------- phase 2: recurrent LIF, single-poll-warp handshake ---------
    const int l  = tid & 31;       // lane
    const int wp = tid >> 5;       // warp 0..7
    const int j  = bid * 32 + l;   // this block's 32 output columns

    // gather word ranges for warps 1..7: 18,18,18,18,18,18,20 (=128 words)
    const int wstart = (wp >= 1) ? 18 * (wp - 1) : 0;
    const int wcnt   = (wp == 7) ? 20 : 18;

    float v = 0.f, rt = 0.f, tl = 1.f;
    const float DECAY = 0.99004983374916805f;   // fp32(exp(-1/100))

    for (int t = 0; t < TT; ++t) {
        float x0 = 0.f, x1 = 0.f, x2 = 0.f, x3 = 0.f;

        if (wp == 0) {
            // issue input-drive prefetch early (latency hidden behind poll)
            x0 = g_Xpart[(size_t)(0 * 320 + t) * NN + j];
            x1 = g_Xpart[(size_t)(1 * 320 + t) * NN + j];
            x2 = g_Xpart[(size_t)(2 * 320 + t) * NN + j];
            x3 = g_Xpart[(size_t)(3 * 320 + t) * NN + j];
            if (t > 0) {
                // ONLY warp in the block touching global flags: lane owns 4 slots
                const unsigned long long* slot = &g_slot[t - 1][4 * l];
                const unsigned want = (unsigned)t;          // producer tag = step+1
                unsigned long long a0, a1, b0, b1;
                bool okA = false, okB = false;
                while (1) {
                    if (!okA) {
                        ldcgv2(slot, a0, a1);
                        okA = ((unsigned)(a0 >> 32) == want) & ((unsigned)(a1 >> 32) == want);
                    }
                    if (!okB) {
                        ldcgv2(slot + 2, b0, b1);
                        okB = ((unsigned)(b0 >> 32) == want) & ((unsigned)(b1 >> 32) == want);
                    }
                    if (__all_sync(0xffffffffu, okA & okB)) break;
                    __nanosleep(30);
                }
                sh_mask[4 * l]     = (unsigned)a0;
                sh_mask[4 * l + 1] = (unsigned)a1;
                sh_mask[4 * l + 2] = (unsigned)b0;
                sh_mask[4 * l + 3] = (unsigned)b1;
            }
        }
        __syncthreads();   // sync_A: masks visible in smem

        float xa = 0.f, xb = 0.f;
        if (wp > 0 && t > 0) {
            for (int k = wstart; k < wstart + wcnt; ++k) {
                unsigned bits = sh_mask[k];       // smem broadcast
                int base = k << 5;
                while (bits) {
                    int b0 = __ffs(bits) - 1; bits &= bits - 1u;
                    if (bits) {
                        int b1 = __ffs(bits) - 1; bits &= bits - 1u;
                        xa += __ldg(&w_rec[(size_t)(base + b0) * NN + j]);
                        xb += __ldg(&w_rec[(size_t)(base + b1) * NN + j]);
                    } else {
                        xa += __ldg(&w_rec[(size_t)(base + b0) * NN + j]);
                    }
                }
            }
        }
        part[wp][l] = xa + xb;
        __syncthreads();   // sync_B: parts ready

        if (wp == 0) {
            float xt = ((part[1][l] + part[2][l]) + (part[3][l] + part[4][l]))
                     + ((part[5][l] + part[6][l]) + part[7][l])
                     + ((x0 + x1) + (x2 + x3));
            // LIF dynamics, exact reference order
            v *= DECAY;
            float xin = (rt > 0.f) ? 0.f : xt;
            rt -= 1.f;
            v += xin;
            bool sp = (v >= 10.f);
            if (sp) { tl = (float)t / 300.0f; rt = 1.f; v = 0.f; }

            // publish FIRST (single 64-bit tagged store), then outputs
            unsigned ball = __ballot_sync(0xffffffffu, sp);
            if (t < TT - 1 && l == 0)
                stcg64(&g_slot[t][bid],
                       ((unsigned long long)(unsigned)(t + 1) << 32) |
                       (unsigned long long)ball);
            out[(size_t)t * NN + j]            = sp ? 1.f : 0.f;
            out[(size_t)(TT + t) * NN + j]     = tl;
            out[(size_t)(2 * TT + t) * NN + j] = v;
        }
        // no trailing sync needed: gather warps can't overwrite part[] for step
        // t+1 until they pass sync_A(t+1), which warp 0 only joins after it has
        // consumed part[] of step t.
    }
}

// ---------------- launch ----------------
extern "C" void kernel_launch(void* const* d_in, const int* in_sizes, int n_in,
                              void* d_out, int out_size) {
    const int* inp; const float* w; const float* w_rec;
    if (in_sizes[0] == TT * NN) {
        inp = (const int*)d_in[0]; w = (const float*)d_in[1]; w_rec = (const float*)d_in[2];
    } else if (n_in > 1 && in_sizes[1] == TT * NN) {
        inp = (const int*)d_in[1]; w = (const float*)d_in[0]; w_rec = (const float*)d_in[2];
    } else {
        inp = (const int*)d_in[2]; w = (const float*)d_in[0]; w_rec = (const float*)d_in[1];
    }
    snn_kernel<<<NBLK, NTHR>>>(inp, w, w_rec, (float*)d_out);
}

// round 6
// speedup vs baseline: 1.6435x; 1.3361x over previous
#include <cuda_runtime.h>

#define NN   4096
#define TT   300
#define TW   10          // 320 bits >= 300 timesteps
#define NBLK 128         // persistent blocks for recurrent kernel
#define NT1  256
#define NT2  512

// ---------------- device scratch (static globals; no allocations) ----------------
__device__ unsigned g_mask[NN * TW];          // bit t of inp[t][i], i-major
__device__ float    g_Xpart[4ull * 320 * NN]; // 4 i-quarter partials of inp@W
__device__ __align__(256) unsigned long long g_slot[TT][NBLK];   // {tag=t+1, mask}

__device__ __forceinline__ void ldcgv2(const unsigned long long* p,
                                       unsigned long long& a, unsigned long long& b) {
    asm volatile("ld.global.cg.v2.u64 {%0,%1}, [%2];" : "=l"(a), "=l"(b) : "l"(p));
}
__device__ __forceinline__ void stcg64(unsigned long long* p, unsigned long long v) {
    asm volatile("st.global.cg.b64 [%0], %1;" :: "l"(p), "l"(v));
}

// ---------------- kernel 1: pack inp bits + clear slot tags ----------------
__global__ void pack_kernel(const int* __restrict__ inp) {
    int gid = blockIdx.x * blockDim.x + threadIdx.x;   // 4096 threads
    for (int u = gid; u < TT * NBLK; u += 4096)
        ((unsigned long long*)g_slot)[u] = 0ull;
    int i = gid;
    if (i < NN) {
        for (int w = 0; w < TW; ++w) {
            unsigned m = 0u;
            int tb = w * 32;
            #pragma unroll
            for (int b = 0; b < 32; ++b) {
                int t = tb + b;
                if (t < TT) m |= (((unsigned)inp[(size_t)t * NN + i]) & 1u) << b;
            }
            g_mask[i * TW + w] = m;
        }
    }
}

// ---------------- kernel 2: X partials via packed f32x2 FFMA (exact) ----------
// 640 blocks, one tile each: (cc 0..15 colchunk of 256, q 0..3 i-quarter, word 0..9)
__global__ void __launch_bounds__(NT1) xgemm_kernel(const float* __restrict__ w) {
    __shared__ unsigned long long Adup[128][18];
    const int tid  = threadIdx.x;
    const int tile = blockIdx.x;
    int word = tile % 10;
    int ccq  = tile / 10;
    int cc   = ccq >> 2;
    int q    = ccq & 3;
    int j    = cc * 256 + tid;
    int ibase = q * 1024;

    unsigned long long acc[16];
    #pragma unroll
    for (int k = 0; k < 16; ++k) acc[k] = 0ull;

    for (int sub = 0; sub < 8; ++sub) {
        int ib = ibase + sub * 128;
        __syncthreads();
        for (int e = tid; e < 2048; e += NT1) {
            int ii = e >> 4, tp = e & 15;
            unsigned m  = g_mask[(ib + ii) * TW + word];
            unsigned lo = (m >> (2 * tp))     & 1u ? 0x3f800000u : 0u;
            unsigned hi = (m >> (2 * tp + 1)) & 1u ? 0x3f800000u : 0u;
            Adup[ii][tp] = ((unsigned long long)hi << 32) | lo;
        }
        __syncthreads();
        for (int ii = 0; ii < 128; ++ii) {
            unsigned wu = __float_as_uint(w[(size_t)(ib + ii) * NN + j]);
            unsigned long long wpk;
            asm("mov.b64 %0, {%1, %1};" : "=l"(wpk) : "r"(wu));
            const ulonglong2* ap = (const ulonglong2*)(&Adup[ii][0]);
            #pragma unroll
            for (int k = 0; k < 8; ++k) {
                ulonglong2 a2 = ap[k];
                asm("fma.rn.f32x2 %0, %1, %2, %0;" : "+l"(acc[2*k])   : "l"(wpk), "l"(a2.x));
                asm("fma.rn.f32x2 %0, %1, %2, %0;" : "+l"(acc[2*k+1]) : "l"(wpk), "l"(a2.y));
            }
        }
    }
    #pragma unroll
    for (int tp = 0; tp < 16; ++tp) {
        int t0 = word * 32 + 2 * tp;
        g_Xpart[((size_t)q * 320 + t0)     * NN + j] = __uint_as_float((unsigned)acc[tp]);
        g_Xpart[((size_t)q * 320 + t0 + 1) * NN + j] = __uint_as_float((unsigned)(acc[tp] >> 32));
    }
}

// ---------------- kernel 3: persistent recurrent LIF ----------------
__global__ void __launch_bounds__(NT2, 1)
lif_kernel(const float* __restrict__ w_rec, float* __restrict__ out) {
    __shared__ unsigned sh_mask[128];
    __shared__ int      sh_off[128];
    __shared__ int      sh_total;
    __shared__ int      sh_idx[4352];      // compacted spike rows (<<12), padded
    __shared__ float    part[16][33];

    const int tid = threadIdx.x;
    const int bid = blockIdx.x;
    const int l   = tid & 31;
    const int wp  = tid >> 5;              // warp 0..15
    const int j   = bid * 32 + l;          // this block's 32 output columns

    for (int u = tid; u < 4352; u += NT2) sh_idx[u] = 0;   // safe predication pad
    if (tid == 0) sh_total = 0;

    float v = 0.f, rt = 0.f, tl = 1.f;
    const float DECAY = 0.99004983374916805f;   // fp32(exp(-1/100))

    for (int t = 0; t < TT; ++t) {
        float x0 = 0.f, x1 = 0.f, x2 = 0.f, x3 = 0.f;
        if (wp == 0) {
            // input-drive prefetch (latency hidden behind poll)
            x0 = g_Xpart[(size_t)(0 * 320 + t) * NN + j];
            x1 = g_Xpart[(size_t)(1 * 320 + t) * NN + j];
            x2 = g_Xpart[(size_t)(2 * 320 + t) * NN + j];
            x3 = g_Xpart[(size_t)(3 * 320 + t) * NN + j];
            if (t > 0) {
                // single poll warp: lane owns 4 slots via 2 vectorized loads
                const unsigned long long* slot = &g_slot[t - 1][4 * l];
                const unsigned want = (unsigned)t;
                unsigned long long a0, a1, b0, b1;
                bool okA = false, okB = false;
                while (1) {
                    if (!okA) {
                        ldcgv2(slot, a0, a1);
                        okA = ((unsigned)(a0 >> 32) == want) & ((unsigned)(a1 >> 32) == want);
                    }
                    if (!okB) {
                        ldcgv2(slot + 2, b0, b1);
                        okB = ((unsigned)(b0 >> 32) == want) & ((unsigned)(b1 >> 32) == want);
                    }
                    if (__all_sync(0xffffffffu, okA & okB)) break;
                    __nanosleep(30);
                }
                sh_mask[4 * l]     = (unsigned)a0;
                sh_mask[4 * l + 1] = (unsigned)a1;
                sh_mask[4 * l + 2] = (unsigned)b0;
                sh_mask[4 * l + 3] = (unsigned)b1;
            }
        }
        __syncthreads();   // A: masks ready

        if (t > 0) {
            if (wp == 0) {
                // popc + warp scan -> per-word offsets
                unsigned c0 = __popc(sh_mask[4 * l]);
                unsigned c1 = __popc(sh_mask[4 * l + 1]);
                unsigned c2 = __popc(sh_mask[4 * l + 2]);
                unsigned c3 = __popc(sh_mask[4 * l + 3]);
                unsigned s4 = c0 + c1 + c2 + c3;
                unsigned incl = s4;
                #pragma unroll
                for (int d = 1; d < 32; d <<= 1) {
                    unsigned o = __shfl_up_sync(0xffffffffu, incl, d);
                    if (l >= d) incl += o;
                }
                unsigned excl = incl - s4;
                sh_off[4 * l]     = (int)excl;
                sh_off[4 * l + 1] = (int)(excl + c0);
                sh_off[4 * l + 2] = (int)(excl + c0 + c1);
                sh_off[4 * l + 3] = (int)(excl + c0 + c1 + c2);
                if (l == 31) sh_total = (int)incl;
            }
            __syncthreads();   // B: offsets ready
            if (tid < 128) {   // expand masks -> compacted premultiplied rows
                unsigned bits = sh_mask[tid];
                int o = sh_off[tid];
                int base = tid << 5;
                while (bits) {
                    int b = __ffs(bits) - 1;
                    bits &= bits - 1u;
                    sh_idx[o++] = (base + b) << 12;    // row * NN
                }
            }
            __syncthreads();   // C: index list ready
        }

        // batched gather: 16 warps, 16 independent loads per batch per thread
        {
            const int S = sh_total;
            const float* wr = w_rec + j;
            float acc = 0.f, acc2 = 0.f;
            for (int k = wp; k < S; k += 256) {
                float r[16];
                #pragma unroll
                for (int u = 0; u < 16; ++u) {
                    int kk = k + 16 * u;
                    float rv = 0.f;
                    if (kk < S) rv = __ldg(wr + sh_idx[kk]);
                    r[u] = rv;
                }
                #pragma unroll
                for (int u = 0; u < 16; u += 2) { acc += r[u]; acc2 += r[u + 1]; }
            }
            part[wp][l] = acc + acc2;
        }
        __syncthreads();   // D: partials ready

        if (wp == 0) {
            float xt = (((part[0][l] + part[1][l]) + (part[2][l] + part[3][l]))
                      + ((part[4][l] + part[5][l]) + (part[6][l] + part[7][l])))
                     + (((part[8][l] + part[9][l]) + (part[10][l] + part[11][l]))
                      + ((part[12][l] + part[13][l]) + (part[14][l] + part[15][l])))
                     + ((x0 + x1) + (x2 + x3));
            // LIF dynamics, exact reference order
            v *= DECAY;
            float xin = (rt > 0.f) ? 0.f : xt;
            rt -= 1.f;
            v += xin;
            bool sp = (v >= 10.f);
            if (sp) { tl = (float)t / 300.0f; rt = 1.f; v = 0.f; }

            // publish FIRST, then write outputs
            unsigned ball = __ballot_sync(0xffffffffu, sp);
            if (t < TT - 1 && l == 0)
                stcg64(&g_slot[t][bid],
                       ((unsigned long long)(unsigned)(t + 1) << 32) |
                       (unsigned long long)ball);
            out[(size_t)t * NN + j]            = sp ? 1.f : 0.f;
            out[(size_t)(TT + t) * NN + j]     = tl;
            out[(size_t)(2 * TT + t) * NN + j] = v;
        }
        // no extra sync: warp0 joins A(t+1) only after its epilogue; gather warps
        // write part(t+1) only after C(t+1) > A(t+1).
    }
}

// ---------------- launch ----------------
extern "C" void kernel_launch(void* const* d_in, const int* in_sizes, int n_in,
                              void* d_out, int out_size) {
    const int* inp; const float* w; const float* w_rec;
    if (in_sizes[0] == TT * NN) {
        inp = (const int*)d_in[0]; w = (const float*)d_in[1]; w_rec = (const float*)d_in[2];
    } else if (n_in > 1 && in_sizes[1] == TT * NN) {
        inp = (const int*)d_in[1]; w = (const float*)d_in[0]; w_rec = (const float*)d_in[2];
    } else {
        inp = (const int*)d_in[2]; w = (const float*)d_in[0]; w_rec = (const float*)d_in[1];
    }
    float* out = (float*)d_out;

    pack_kernel<<<16, 256>>>(inp);
    xgemm_kernel<<<640, NT1>>>(w);
    lif_kernel<<<NBLK, NT2>>>(w_rec, out);
}

// round 7
// speedup vs baseline: 1.7552x; 1.0680x over previous
#include <cuda_runtime.h>

#define NN   4096
#define TT   300
#define TW   10          // 320 bits >= 300 timesteps
#define NBLK 128         // persistent blocks for recurrent kernel
#define NT1  256
#define NT2  512

// ---------------- device scratch (static globals; no allocations) ----------------
__device__ unsigned g_mask[NN * TW];          // bit t of inp[t][i], i-major
__device__ float    g_Xpart[4ull * 320 * NN]; // 4 i-quarter partials of inp@W
__device__ __align__(256) unsigned long long g_slot[TT][NBLK];   // {tag=t+1, mask}

__device__ __forceinline__ void ldcgv2(const unsigned long long* p,
                                       unsigned long long& a, unsigned long long& b) {
    asm volatile("ld.global.cg.v2.u64 {%0,%1}, [%2];" : "=l"(a), "=l"(b) : "l"(p));
}
__device__ __forceinline__ void stcg64(unsigned long long* p, unsigned long long v) {
    asm volatile("st.global.cg.b64 [%0], %1;" :: "l"(p), "l"(v));
}

// ---------------- kernel 1: pack inp bits + clear slot tags ----------------
// 160 blocks x 256 thr: block = (i-chunk 0..15, word 0..9); coalesced loads.
__global__ void __launch_bounds__(256) pack_kernel(const int* __restrict__ inp) {
    const int blk  = blockIdx.x;
    const int word = blk % TW;
    const int i    = (blk / TW) * 256 + threadIdx.x;
    unsigned m = 0u;
    const int tb = word * 32;
    #pragma unroll
    for (int b = 0; b < 32; ++b) {
        int t = tb + b;
        if (t < TT) m |= (((unsigned)inp[(size_t)t * NN + i]) & 1u) << b;
    }
    g_mask[i * TW + word] = m;
    int gid = blk * 256 + threadIdx.x;
    if (gid < TT * NBLK) ((unsigned long long*)g_slot)[gid] = 0ull;
}

// ---------------- kernel 2: X partials via packed f32x2 FFMA (exact) ----------
__global__ void __launch_bounds__(NT1) xgemm_kernel(const float* __restrict__ w) {
    __shared__ unsigned long long Adup[128][18];
    const int tid  = threadIdx.x;
    const int tile = blockIdx.x;
    int word = tile % 10;
    int ccq  = tile / 10;
    int cc   = ccq >> 2;
    int q    = ccq & 3;
    int j    = cc * 256 + tid;
    int ibase = q * 1024;

    unsigned long long acc[16];
    #pragma unroll
    for (int k = 0; k < 16; ++k) acc[k] = 0ull;

    for (int sub = 0; sub < 8; ++sub) {
        int ib = ibase + sub * 128;
        __syncthreads();
        for (int e = tid; e < 2048; e += NT1) {
            int ii = e >> 4, tp = e & 15;
            unsigned m  = g_mask[(ib + ii) * TW + word];
            unsigned lo = (m >> (2 * tp))     & 1u ? 0x3f800000u : 0u;
            unsigned hi = (m >> (2 * tp + 1)) & 1u ? 0x3f800000u : 0u;
            Adup[ii][tp] = ((unsigned long long)hi << 32) | lo;
        }
        __syncthreads();
        for (int ii = 0; ii < 128; ++ii) {
            unsigned wu = __float_as_uint(w[(size_t)(ib + ii) * NN + j]);
            unsigned long long wpk;
            asm("mov.b64 %0, {%1, %1};" : "=l"(wpk) : "r"(wu));
            const ulonglong2* ap = (const ulonglong2*)(&Adup[ii][0]);
            #pragma unroll
            for (int k = 0; k < 8; ++k) {
                ulonglong2 a2 = ap[k];
                asm("fma.rn.f32x2 %0, %1, %2, %0;" : "+l"(acc[2*k])   : "l"(wpk), "l"(a2.x));
                asm("fma.rn.f32x2 %0, %1, %2, %0;" : "+l"(acc[2*k+1]) : "l"(wpk), "l"(a2.y));
            }
        }
    }
    #pragma unroll
    for (int tp = 0; tp < 16; ++tp) {
        int t0 = word * 32 + 2 * tp;
        g_Xpart[((size_t)q * 320 + t0)     * NN + j] = __uint_as_float((unsigned)acc[tp]);
        g_Xpart[((size_t)q * 320 + t0 + 1) * NN + j] = __uint_as_float((unsigned)(acc[tp] >> 32));
    }
}

// ---------------- kernel 3: persistent recurrent LIF (2 syncs/step) ----------
__global__ void __launch_bounds__(NT2, 1)
lif_kernel(const float* __restrict__ w_rec, float* __restrict__ out) {
    __shared__ int   sh_idx[NN];          // compacted spike rows (premult by NN)
    __shared__ int   sh_total;
    __shared__ float part[16][33];

    const int tid = threadIdx.x;
    const int bid = blockIdx.x;
    const int l   = tid & 31;
    const int wp  = tid >> 5;              // warp 0..15
    const int j   = bid * 32 + l;          // this block's 32 output columns

    if (tid == 0) sh_total = 0;

    float v = 0.f, rt = 0.f, tl = 1.f;
    const float DECAY = 0.99004983374916805f;   // fp32(exp(-1/100))

    for (int t = 0; t < TT; ++t) {
        float x0 = 0.f, x1 = 0.f, x2 = 0.f, x3 = 0.f;
        if (wp == 0) {
            // input-drive prefetch (latency hidden behind poll)
            x0 = g_Xpart[(size_t)(0 * 320 + t) * NN + j];
            x1 = g_Xpart[(size_t)(1 * 320 + t) * NN + j];
            x2 = g_Xpart[(size_t)(2 * 320 + t) * NN + j];
            x3 = g_Xpart[(size_t)(3 * 320 + t) * NN + j];
            if (t > 0) {
                // --- poll: lane owns 4 slots (2 vectorized loads), tight spin ---
                const unsigned long long* slot = &g_slot[t - 1][4 * l];
                const unsigned want = (unsigned)t;
                unsigned long long a0, a1, b0, b1;
                bool okA = false, okB = false;
                while (1) {
                    if (!okA) {
                        ldcgv2(slot, a0, a1);
                        okA = ((unsigned)(a0 >> 32) == want) & ((unsigned)(a1 >> 32) == want);
                    }
                    if (!okB) {
                        ldcgv2(slot + 2, b0, b1);
                        okB = ((unsigned)(b0 >> 32) == want) & ((unsigned)(b1 >> 32) == want);
                    }
                    if (__all_sync(0xffffffffu, okA & okB)) break;
                }
                // --- scan (in registers) ---
                unsigned m0 = (unsigned)a0, m1 = (unsigned)a1;
                unsigned m2 = (unsigned)b0, m3 = (unsigned)b1;
                unsigned c0 = __popc(m0), c1 = __popc(m1);
                unsigned c2 = __popc(m2), c3 = __popc(m3);
                unsigned s4 = c0 + c1 + c2 + c3;
                unsigned incl = s4;
                #pragma unroll
                for (int d = 1; d < 32; d <<= 1) {
                    unsigned o = __shfl_up_sync(0xffffffffu, incl, d);
                    if (l >= d) incl += o;
                }
                if (l == 31) sh_total = (int)incl;
                int o = (int)(incl - s4);
                // --- expand to compacted premultiplied row list ---
                int base = (4 * l) << 5;
                while (m0) { int b = __ffs(m0) - 1; m0 &= m0 - 1u; sh_idx[o++] = (base + b) << 12; }
                base += 32;
                while (m1) { int b = __ffs(m1) - 1; m1 &= m1 - 1u; sh_idx[o++] = (base + b) << 12; }
                base += 32;
                while (m2) { int b = __ffs(m2) - 1; m2 &= m2 - 1u; sh_idx[o++] = (base + b) << 12; }
                base += 32;
                while (m3) { int b = __ffs(m3) - 1; m3 &= m3 - 1u; sh_idx[o++] = (base + b) << 12; }
            }
        }
        __syncthreads();   // S1: sh_idx + sh_total ready

        // batched gather: all 16 warps, 16 independent loads/thread per batch
        {
            const int S = sh_total;
            const float* wr = w_rec + j;
            float acc = 0.f, acc2 = 0.f;
            for (int k0 = wp * 16; k0 < S; k0 += 256) {
                float r[16];
                #pragma unroll
                for (int u = 0; u < 16; ++u) {
                    int kk = k0 + u;
                    float rv = 0.f;
                    if (kk < S) rv = __ldg(wr + sh_idx[kk]);
                    r[u] = rv;
                }
                #pragma unroll
                for (int u = 0; u < 16; u += 2) { acc += r[u]; acc2 += r[u + 1]; }
            }
            part[wp][l] = acc + acc2;
        }
        __syncthreads();   // S2: partials ready

        if (wp == 0) {
            float xt = (((part[0][l] + part[1][l]) + (part[2][l] + part[3][l]))
                      + ((part[4][l] + part[5][l]) + (part[6][l] + part[7][l])))
                     + (((part[8][l] + part[9][l]) + (part[10][l] + part[11][l]))
                      + ((part[12][l] + part[13][l]) + (part[14][l] + part[15][l])))
                     + ((x0 + x1) + (x2 + x3));
            // LIF dynamics, exact reference order
            v *= DECAY;
            float xin = (rt > 0.f) ? 0.f : xt;
            rt -= 1.f;
            v += xin;
            bool sp = (v >= 10.f);
            if (sp) { tl = (float)t / 300.0f; rt = 1.f; v = 0.f; }

            // publish FIRST, then write outputs
            unsigned ball = __ballot_sync(0xffffffffu, sp);
            if (t < TT - 1 && l == 0)
                stcg64(&g_slot[t][bid],
                       ((unsigned long long)(unsigned)(t + 1) << 32) |
                       (unsigned long long)ball);
            out[(size_t)t * NN + j]            = sp ? 1.f : 0.f;
            out[(size_t)(TT + t) * NN + j]     = tl;
            out[(size_t)(2 * TT + t) * NN + j] = v;
        }
        // no extra syncs: warps 1-15 park at S1(t+1) until warp 0 (which reads
        // part[] and writes sh_idx for t+1 first) arrives; WAR-safe by construction.
    }
}

// ---------------- launch ----------------
extern "C" void kernel_launch(void* const* d_in, const int* in_sizes, int n_in,
                              void* d_out, int out_size) {
    const int* inp; const float* w; const float* w_rec;
    if (in_sizes[0] == TT * NN) {
        inp = (const int*)d_in[0]; w = (const float*)d_in[1]; w_rec = (const float*)d_in[2];
    } else if (n_in > 1 && in_sizes[1] == TT * NN) {
        inp = (const int*)d_in[1]; w = (const float*)d_in[0]; w_rec = (const float*)d_in[2];
    } else {
        inp = (const int*)d_in[2]; w = (const float*)d_in[0]; w_rec = (const float*)d_in[1];
    }
    float* out = (float*)d_out;

    pack_kernel<<<160, 256>>>(inp);
    xgemm_kernel<<<640, NT1>>>(w);
    lif_kernel<<<NBLK, NT2>>>(w_rec, out);
}

// round 8
// speedup vs baseline: 1.7986x; 1.0247x over previous
#include <cuda_runtime.h>

#define NN   4096
#define TT   300
#define TW   10
#define NBLK 128
#define NT1  256
#define NT2  512

// ---------------- device scratch ----------------
__device__ unsigned g_mask[NN * TW];
__device__ float    g_Xpart[4ull * 320 * NN];
__device__ __align__(256) unsigned long long g_slot[TT][NBLK];   // {tag=t+1, mask}

__device__ __forceinline__ void ldcgv2(const unsigned long long* p,
                                       unsigned long long& a, unsigned long long& b) {
    asm volatile("ld.global.cg.v2.u64 {%0,%1}, [%2];" : "=l"(a), "=l"(b) : "l"(p));
}
__device__ __forceinline__ void stcg64(unsigned long long* p, unsigned long long v) {
    asm volatile("st.global.cg.b64 [%0], %1;" :: "l"(p), "l"(v));
}
__device__ __forceinline__ float4 ldcg128(const float* p) {
    float4 v;
    asm volatile("ld.global.cg.v4.f32 {%0,%1,%2,%3}, [%4];"
                 : "=f"(v.x), "=f"(v.y), "=f"(v.z), "=f"(v.w) : "l"(p));
    return v;
}

// ---------------- kernel 1: pack inp bits + clear slot tags ----------------
__global__ void __launch_bounds__(256) pack_kernel(const int* __restrict__ inp) {
    const int blk  = blockIdx.x;
    const int word = blk % TW;
    const int i    = (blk / TW) * 256 + threadIdx.x;
    unsigned m = 0u;
    const int tb = word * 32;
    #pragma unroll
    for (int b = 0; b < 32; ++b) {
        int t = tb + b;
        if (t < TT) m |= (((unsigned)inp[(size_t)t * NN + i]) & 1u) << b;
    }
    g_mask[i * TW + word] = m;
    int gid = blk * 256 + threadIdx.x;
    if (gid < TT * NBLK) ((unsigned long long*)g_slot)[gid] = 0ull;
}

// ---------------- kernel 2: X partials via packed f32x2 FFMA (exact) ----------
__global__ void __launch_bounds__(NT1) xgemm_kernel(const float* __restrict__ w) {
    __shared__ unsigned long long Adup[128][18];
    const int tid  = threadIdx.x;
    const int tile = blockIdx.x;
    int word = tile % 10;
    int ccq  = tile / 10;
    int cc   = ccq >> 2;
    int q    = ccq & 3;
    int j    = cc * 256 + tid;
    int ibase = q * 1024;

    unsigned long long acc[16];
    #pragma unroll
    for (int k = 0; k < 16; ++k) acc[k] = 0ull;

    for (int sub = 0; sub < 8; ++sub) {
        int ib = ibase + sub * 128;
        __syncthreads();
        for (int e = tid; e < 2048; e += NT1) {
            int ii = e >> 4, tp = e & 15;
            unsigned m  = g_mask[(ib + ii) * TW + word];
            unsigned lo = (m >> (2 * tp))     & 1u ? 0x3f800000u : 0u;
            unsigned hi = (m >> (2 * tp + 1)) & 1u ? 0x3f800000u : 0u;
            Adup[ii][tp] = ((unsigned long long)hi << 32) | lo;
        }
        __syncthreads();
        for (int ii = 0; ii < 128; ++ii) {
            unsigned wu = __float_as_uint(w[(size_t)(ib + ii) * NN + j]);
            unsigned long long wpk;
            asm("mov.b64 %0, {%1, %1};" : "=l"(wpk) : "r"(wu));
            const ulonglong2* ap = (const ulonglong2*)(&Adup[ii][0]);
            #pragma unroll
            for (int k = 0; k < 8; ++k) {
                ulonglong2 a2 = ap[k];
                asm("fma.rn.f32x2 %0, %1, %2, %0;" : "+l"(acc[2*k])   : "l"(wpk), "l"(a2.x));
                asm("fma.rn.f32x2 %0, %1, %2, %0;" : "+l"(acc[2*k+1]) : "l"(wpk), "l"(a2.y));
            }
        }
    }
    #pragma unroll
    for (int tp = 0; tp < 16; ++tp) {
        int t0 = word * 32 + 2 * tp;
        g_Xpart[((size_t)q * 320 + t0)     * NN + j] = __uint_as_float((unsigned)acc[tp]);
        g_Xpart[((size_t)q * 320 + t0 + 1) * NN + j] = __uint_as_float((unsigned)(acc[tp] >> 32));
    }
}

// ---------------- kernel 3: persistent recurrent LIF (LDG.128 gather) --------
__global__ void __launch_bounds__(NT2, 1)
lif_kernel(const float* __restrict__ w_rec, float* __restrict__ out) {
    __shared__ unsigned sh_mask[128];
    __shared__ int      sh_off[128];
    __shared__ int      sh_total;
    __shared__ int      sh_idx[NN];        // compacted spike rows (premult by NN)
    __shared__ float4   part4[16][9];      // per-warp column partials

    const int tid = threadIdx.x;
    const int bid = blockIdx.x;
    const int l   = tid & 31;
    const int wp  = tid >> 5;              // warp 0..15
    const int sub = l >> 3;                // row-within-quad 0..3
    const int ln8 = l & 7;                 // 16B chunk within 128B row segment
    const int j0  = bid * 32;              // block's 32 columns

    if (tid == 0) sh_total = 0;

    float v = 0.f, rt = 0.f, tl = 1.f;
    const float DECAY = 0.99004983374916805f;   // fp32(exp(-1/100))

    for (int t = 0; t < TT; ++t) {
        float x0 = 0.f, x1 = 0.f, x2 = 0.f, x3 = 0.f;
        if (wp == 0) {
            const int j = j0 + l;
            // input-drive prefetch (in flight during poll)
            x0 = g_Xpart[(size_t)(0 * 320 + t) * NN + j];
            x1 = g_Xpart[(size_t)(1 * 320 + t) * NN + j];
            x2 = g_Xpart[(size_t)(2 * 320 + t) * NN + j];
            x3 = g_Xpart[(size_t)(3 * 320 + t) * NN + j];
            if (t > 0) {
                // poll: lane owns 4 slots via 2 independent v2 loads, tight spin
                const unsigned long long* slot = &g_slot[t - 1][4 * l];
                const unsigned want = (unsigned)t;
                unsigned long long a0, a1, b0, b1;
                bool okA = false, okB = false;
                while (1) {
                    if (!okA) {
                        ldcgv2(slot, a0, a1);
                        okA = ((unsigned)(a0 >> 32) == want) & ((unsigned)(a1 >> 32) == want);
                    }
                    if (!okB) {
                        ldcgv2(slot + 2, b0, b1);
                        okB = ((unsigned)(b0 >> 32) == want) & ((unsigned)(b1 >> 32) == want);
                    }
                    if (__all_sync(0xffffffffu, okA & okB)) break;
                }
                // scan in registers -> per-word offsets
                unsigned m0 = (unsigned)a0, m1 = (unsigned)a1;
                unsigned m2 = (unsigned)b0, m3 = (unsigned)b1;
                unsigned c0 = __popc(m0), c1 = __popc(m1);
                unsigned c2 = __popc(m2), c3 = __popc(m3);
                unsigned s4 = c0 + c1 + c2 + c3;
                unsigned incl = s4;
                #pragma unroll
                for (int d = 1; d < 32; d <<= 1) {
                    unsigned o = __shfl_up_sync(0xffffffffu, incl, d);
                    if (l >= d) incl += o;
                }
                if (l == 31) sh_total = (int)incl;
                unsigned excl = incl - s4;
                sh_mask[4 * l]     = m0;  sh_off[4 * l]     = (int)excl;
                sh_mask[4 * l + 1] = m1;  sh_off[4 * l + 1] = (int)(excl + c0);
                sh_mask[4 * l + 2] = m2;  sh_off[4 * l + 2] = (int)(excl + c0 + c1);
                sh_mask[4 * l + 3] = m3;  sh_off[4 * l + 3] = (int)(excl + c0 + c1 + c2);
            }
        }
        __syncthreads();   // S1a: masks + offsets ready

        if (t > 0 && tid < 128) {   // parallel expansion: one word per thread
            unsigned bits = sh_mask[tid];
            int o = sh_off[tid];
            int base = tid << 5;
            while (bits) {
                int b = __ffs(bits) - 1;
                bits &= bits - 1u;
                sh_idx[o++] = (base + b) << 12;    // row * NN
            }
        }
        __syncthreads();   // S1b: index list ready

        // gather: warp handles 4 rows per LDG.128 wave, batch of 8 in flight
        {
            const int S = sh_total;
            const float* wr = w_rec + j0 + (ln8 << 2);
            float4 acc = make_float4(0.f, 0.f, 0.f, 0.f);
            const int myrow = (wp << 2) + sub;
            for (int base = 0; base < S; base += 512) {
                float4 rv[8];
                #pragma unroll
                for (int u = 0; u < 8; ++u) {
                    int kk = base + (u << 6) + myrow;
                    float4 z = make_float4(0.f, 0.f, 0.f, 0.f);
                    if (kk < S) z = ldcg128(wr + sh_idx[kk]);
                    rv[u] = z;
                }
                #pragma unroll
                for (int u = 0; u < 8; ++u) {
                    acc.x += rv[u].x; acc.y += rv[u].y;
                    acc.z += rv[u].z; acc.w += rv[u].w;
                }
            }
            // reduce across the 4 sub-rows within the warp
            acc.x += __shfl_down_sync(0xffffffffu, acc.x, 16);
            acc.y += __shfl_down_sync(0xffffffffu, acc.y, 16);
            acc.z += __shfl_down_sync(0xffffffffu, acc.z, 16);
            acc.w += __shfl_down_sync(0xffffffffu, acc.w, 16);
            acc.x += __shfl_down_sync(0xffffffffu, acc.x, 8);
            acc.y += __shfl_down_sync(0xffffffffu, acc.y, 8);
            acc.z += __shfl_down_sync(0xffffffffu, acc.z, 8);
            acc.w += __shfl_down_sync(0xffffffffu, acc.w, 8);
            if (l < 8) part4[wp][l] = acc;
        }
        __syncthreads();   // S2: partials ready

        if (wp == 0) {
            const float* pf = (const float*)part4;   // row stride 9*4 = 36 floats
            float xr = 0.f;
            #pragma unroll
            for (int w16 = 0; w16 < 16; ++w16) xr += pf[w16 * 36 + l];
            float xt = xr + ((x0 + x1) + (x2 + x3));
            // LIF dynamics, exact reference order
            v *= DECAY;
            float xin = (rt > 0.f) ? 0.f : xt;
            rt -= 1.f;
            v += xin;
            bool sp = (v >= 10.f);
            if (sp) { tl = (float)t / 300.0f; rt = 1.f; v = 0.f; }

            // publish FIRST, then write outputs
            unsigned ball = __ballot_sync(0xffffffffu, sp);
            if (t < TT - 1 && l == 0)
                stcg64(&g_slot[t][bid],
                       ((unsigned long long)(unsigned)(t + 1) << 32) |
                       (unsigned long long)ball);
            const int j = j0 + l;
            out[(size_t)t * NN + j]            = sp ? 1.f : 0.f;
            out[(size_t)(TT + t) * NN + j]     = tl;
            out[(size_t)(2 * TT + t) * NN + j] = v;
        }
        // loop-back WAR safety: sh_mask/sh_idx for t+1 are written only after
        // S1a(t+1)/S2(t), which every reader of step-t data has already passed.
    }
}

// ---------------- launch ----------------
extern "C" void kernel_launch(void* const* d_in, const int* in_sizes, int n_in,
                              void* d_out, int out_size) {
    const int* inp; const float* w; const float* w_rec;
    if (in_sizes[0] == TT * NN) {
        inp = (const int*)d_in[0]; w = (const float*)d_in[1]; w_rec = (const float*)d_in[2];
    } else if (n_in > 1 && in_sizes[1] == TT * NN) {
        inp = (const int*)d_in[1]; w = (const float*)d_in[0]; w_rec = (const float*)d_in[2];
    } else {
        inp = (const int*)d_in[2]; w = (const float*)d_in[0]; w_rec = (const float*)d_in[1];
    }
    float* out = (float*)d_out;

    pack_kernel<<<160, 256>>>(inp);
    xgemm_kernel<<<640, NT1>>>(w);
    lif_kernel<<<NBLK, NT2>>>(w_rec, out);
}